// round 14
// baseline (speedup 1.0000x reference)
#include <cuda_runtime.h>
#include <cuda_bf16.h>

static constexpr int CHAN   = 64;
static constexpr int NSPLIT = 8;

// 16 threads per row; thread owns one float4 (4 channels) of the 64-channel row.
// Single pass: read row once, compute 8 logits (partial FMA + 16-lane shfl
// reduction), argmax, then 8 coalesced streaming float4 stores (1 data + 7 zero).
__global__ __launch_bounds__(256)
void voxel_wise_mapping_kernel(const float* __restrict__ feat,
                               const float* __restrict__ W,
                               const float* __restrict__ b,
                               float* __restrict__ out,
                               int n)
{
    __shared__ float Ws[CHAN * NSPLIT];   // 2 KB, layout [c][j]
    __shared__ float bs[NSPLIT];

    for (int i = threadIdx.x; i < CHAN * NSPLIT; i += blockDim.x)
        Ws[i] = __ldg(&W[i]);
    if (threadIdx.x < NSPLIT)
        bs[threadIdx.x] = __ldg(&b[threadIdx.x]);
    __syncthreads();

    const int gid = blockIdx.x * blockDim.x + threadIdx.x;
    const int row = gid >> 4;       // 16 threads per row
    const int l   = gid & 15;       // lane within the 16-group
    if (row >= n) return;

    // Coalesced 256B-per-row read (16 lanes x float4)
    const float4 f = reinterpret_cast<const float4*>(feat)[(size_t)row * 16 + l];
    const float fv[4] = {f.x, f.y, f.z, f.w};

    // Partial logits over this thread's 4 channels
    float acc[NSPLIT];
#pragma unroll
    for (int j = 0; j < NSPLIT; ++j) acc[j] = 0.0f;

    const int c0 = l * 4;
#pragma unroll
    for (int k = 0; k < 4; ++k) {
        const float v = fv[k];
        const float* wrow = &Ws[(c0 + k) * NSPLIT];
#pragma unroll
        for (int j = 0; j < NSPLIT; ++j)
            acc[j] = fmaf(v, wrow[j], acc[j]);
    }

    // Reduce across the 16-lane group (xor 8,4,2,1 stays within the group)
#pragma unroll
    for (int off = 8; off >= 1; off >>= 1) {
#pragma unroll
        for (int j = 0; j < NSPLIT; ++j)
            acc[j] += __shfl_xor_sync(0xFFFFFFFFu, acc[j], off);
    }

    // Argmax with first-max tie-break (strict >), matching jnp.argmax
    int   best = 0;
    float bv   = acc[0] + bs[0];
#pragma unroll
    for (int j = 1; j < NSPLIT; ++j) {
        const float v = acc[j] + bs[j];
        if (v > bv) { bv = v; best = j; }
    }

    // 8 slabs of [n, 64]; streaming stores (write-once output, bypass-friendly)
    const float4 z = make_float4(0.f, 0.f, 0.f, 0.f);
    const size_t slab_stride = (size_t)n * 16;   // in float4 units
    float4* o = reinterpret_cast<float4*>(out) + (size_t)row * 16 + l;
#pragma unroll
    for (int j = 0; j < NSPLIT; ++j) {
        __stcs(o, (j == best) ? f : z);
        o += slab_stride;
    }
}

extern "C" void kernel_launch(void* const* d_in, const int* in_sizes, int n_in,
                              void* d_out, int out_size)
{
    const float* feat = (const float*)d_in[0];   // [N, 64]
    const float* W    = (const float*)d_in[1];   // [64, 8]
    const float* b    = (const float*)d_in[2];   // [8]
    float* out        = (float*)d_out;           // [8, N, 64]

    const int n = in_sizes[0] / CHAN;            // 400000
    const int threads = 256;
    const int total   = n * 16;                  // 16 threads per row
    const int blocks  = (total + threads - 1) / threads;

    voxel_wise_mapping_kernel<<<blocks, threads>>>(feat, W, b, out, n);
}

// round 16
// speedup vs baseline: 1.7231x; 1.7231x over previous
#include <cuda_runtime.h>
#include <cuda_bf16.h>

static constexpr int CHAN   = 64;
static constexpr int NSPLIT = 8;

// 16 threads per row; thread owns one float4 (4 channels) of the 64-channel row.
// W staged in shared TRANSPOSED as WT[j][c] so each lane's weight fetch for
// split j is one conflict-cheap float4 LDS (lane l reads WT[j][4l..4l+3]):
// 2-phase crossbar floor instead of the 16-way conflict of the [c][j] layout.
__global__ __launch_bounds__(256)
void voxel_wise_mapping_kernel(const float* __restrict__ feat,
                               const float* __restrict__ W,
                               const float* __restrict__ b,
                               float* __restrict__ out,
                               int n)
{
    __shared__ float WT[NSPLIT][CHAN];   // 2 KB, transposed [j][c]
    __shared__ float bs[NSPLIT];

    for (int i = threadIdx.x; i < CHAN * NSPLIT; i += blockDim.x) {
        const int c = i >> 3;            // W is [c][j] row-major in gmem
        const int j = i & 7;
        WT[j][c] = __ldg(&W[i]);
    }
    if (threadIdx.x < NSPLIT)
        bs[threadIdx.x] = __ldg(&b[threadIdx.x]);
    __syncthreads();

    const int gid = blockIdx.x * blockDim.x + threadIdx.x;
    const int row = gid >> 4;       // 16 threads per row
    const int l   = gid & 15;       // lane within the 16-group
    if (row >= n) return;

    // Coalesced 256B-per-row read (16 lanes x float4)
    const float4 f = reinterpret_cast<const float4*>(feat)[(size_t)row * 16 + l];

    // Partial logits: one float4 weight fetch per split, 4 FMAs each
    float acc[NSPLIT];
#pragma unroll
    for (int j = 0; j < NSPLIT; ++j) {
        const float4 w = *reinterpret_cast<const float4*>(&WT[j][l * 4]);
        float s = f.x * w.x;
        s = fmaf(f.y, w.y, s);
        s = fmaf(f.z, w.z, s);
        s = fmaf(f.w, w.w, s);
        acc[j] = s;
    }

    // Reduce across the 16-lane group (xor 8,4,2,1 stays within the group)
#pragma unroll
    for (int off = 8; off >= 1; off >>= 1) {
#pragma unroll
        for (int j = 0; j < NSPLIT; ++j)
            acc[j] += __shfl_xor_sync(0xFFFFFFFFu, acc[j], off);
    }

    // Argmax with first-max tie-break (strict >), matching jnp.argmax
    int   best = 0;
    float bv   = acc[0] + bs[0];
#pragma unroll
    for (int j = 1; j < NSPLIT; ++j) {
        const float v = acc[j] + bs[j];
        if (v > bv) { bv = v; best = j; }
    }

    // 8 slabs of [n, 64]; streaming stores (write-once output, bypass-friendly)
    const float4 z = make_float4(0.f, 0.f, 0.f, 0.f);
    const size_t slab_stride = (size_t)n * 16;   // in float4 units
    float4* o = reinterpret_cast<float4*>(out) + (size_t)row * 16 + l;
#pragma unroll
    for (int j = 0; j < NSPLIT; ++j) {
        __stcs(o, (j == best) ? f : z);
        o += slab_stride;
    }
}

extern "C" void kernel_launch(void* const* d_in, const int* in_sizes, int n_in,
                              void* d_out, int out_size)
{
    const float* feat = (const float*)d_in[0];   // [N, 64]
    const float* W    = (const float*)d_in[1];   // [64, 8]
    const float* b    = (const float*)d_in[2];   // [8]
    float* out        = (float*)d_out;           // [8, N, 64]

    const int n = in_sizes[0] / CHAN;            // 400000
    const int threads = 256;
    const int total   = n * 16;                  // 16 threads per row
    const int blocks  = (total + threads - 1) / threads;

    voxel_wise_mapping_kernel<<<blocks, threads>>>(feat, W, b, out, n);
}